// round 3
// baseline (speedup 1.0000x reference)
#include <cuda_runtime.h>
#include <cuda_bf16.h>
#include <math.h>

// Problem constants
#define BDIM 8
#define SDIM 1024
#define HDIM 768
#define NH   12
#define HD   64
#define MROWS (BDIM*SDIM)        // 8192
#define QKVLD 2304               // 3*HDIM
#define NROWSEL (BDIM*NH*SDIM)   // 98304 rows (b,h,q)
#define TINYF 1.17549435e-38f

// Scratch (allocation-free rule: __device__ globals)
__device__ float d_QKV[MROWS * QKVLD];          // [8192, 2304] = q|k|v
__device__ float d_Ag[MROWS * HDIM];            // gathered V rows
__device__ unsigned char d_code[BDIM*NH*SDIM];  // centroid code, layout [b,h,s]
__device__ int d_kstar[BDIM*NH*SDIM];           // selected key per (b,h,q)

// ---------------- JAX threefry2x32 (20 rounds) ----------------
// Verified against Random123 KAT: key(0,0) ctr(0,0) -> (0x6b200159, 0x99ba4efe)
__device__ __forceinline__ void threefry(unsigned k0, unsigned k1,
                                         unsigned &x0, unsigned &x1) {
  unsigned k2 = k0 ^ k1 ^ 0x1BD11BDAu;
  x0 += k0; x1 += k1;
#define TF_R(r) { x0 += x1; x1 = __funnelshift_l(x1, x1, r); x1 ^= x0; }
  TF_R(13) TF_R(15) TF_R(26) TF_R(6)
  x0 += k1; x1 += k2 + 1u;
  TF_R(17) TF_R(29) TF_R(16) TF_R(24)
  x0 += k2; x1 += k0 + 2u;
  TF_R(13) TF_R(15) TF_R(26) TF_R(6)
  x0 += k0; x1 += k1 + 3u;
  TF_R(17) TF_R(29) TF_R(16) TF_R(24)
  x0 += k1; x1 += k2 + 4u;
  TF_R(13) TF_R(15) TF_R(26) TF_R(6)
  x0 += k2; x1 += k0 + 5u;
#undef TF_R
}

// jax_threefry_partitionable=True (default since jax 0.5) 32-bit random bits:
// ctr64 = flat index i (< 2^32 here -> hi word 0), bits = out0 ^ out1.
__device__ __forceinline__ unsigned tf_bits(unsigned k0, unsigned k1, unsigned lo) {
  unsigned x0 = 0u, x1 = lo;
  threefry(k0, k1, x0, x1);
  return x0 ^ x1;
}

// u in [tiny, 1) exactly as jax.random.uniform(minval=tiny, maxval=1)
__device__ __forceinline__ float u_from_v23(unsigned v23) {
  float f = __uint_as_float(v23 | 0x3f800000u) - 1.0f;
  return fmaxf(f, TINYF);
}
__device__ __forceinline__ float gumbel_of_u(float u) {
  // double-precision path -> correctly rounded f32 gumbel
  return (float)(-log(-log((double)u)));
}

// ---------------- SGEMM (f32 FFMA, 128x128x8, bias, col-offset) -------------
__global__ __launch_bounds__(256) void sgemm_bias(
    const float* __restrict__ A, const float* __restrict__ B,
    const float* __restrict__ bias, float* __restrict__ C,
    int K, int lda, int ldb, int ldc, int coff)
{
  __shared__ float As[8][128];
  __shared__ float Bs[8][128];
  int tid = threadIdx.x;
  int bm = blockIdx.y, bn = blockIdx.x;
  int tx = tid & 15, ty = tid >> 4;
  int arow = tid >> 1, acol = (tid & 1) * 4;
  int brow = tid >> 5, bcol = (tid & 31) * 4;

  float acc[8][8];
#pragma unroll
  for (int i = 0; i < 8; i++)
#pragma unroll
    for (int j = 0; j < 8; j++) acc[i][j] = 0.f;

  for (int k0 = 0; k0 < K; k0 += 8) {
    float4 av = *(const float4*)(A + (size_t)(bm*128 + arow)*lda + k0 + acol);
    float4 bv = *(const float4*)(B + (size_t)(k0 + brow)*ldb + bn*128 + bcol);
    __syncthreads();
    As[acol+0][arow] = av.x;
    As[acol+1][arow] = av.y;
    As[acol+2][arow] = av.z;
    As[acol+3][arow] = av.w;
    *(float4*)&Bs[brow][bcol] = bv;
    __syncthreads();
#pragma unroll
    for (int kk = 0; kk < 8; kk++) {
      float4 a0 = *(const float4*)&As[kk][ty*8];
      float4 a1 = *(const float4*)&As[kk][ty*8+4];
      float4 b0 = *(const float4*)&Bs[kk][tx*8];
      float4 b1 = *(const float4*)&Bs[kk][tx*8+4];
      float am[8] = {a0.x,a0.y,a0.z,a0.w,a1.x,a1.y,a1.z,a1.w};
      float bb[8] = {b0.x,b0.y,b0.z,b0.w,b1.x,b1.y,b1.z,b1.w};
#pragma unroll
      for (int i = 0; i < 8; i++)
#pragma unroll
        for (int j = 0; j < 8; j++) acc[i][j] += am[i]*bb[j];
    }
  }
#pragma unroll
  for (int i = 0; i < 8; i++) {
    int row = bm*128 + ty*8 + i;
#pragma unroll
    for (int j4 = 0; j4 < 2; j4++) {
      int col = bn*128 + tx*8 + j4*4;
      float4 o;
      o.x = acc[i][j4*4+0] + bias[col+0];
      o.y = acc[i][j4*4+1] + bias[col+1];
      o.z = acc[i][j4*4+2] + bias[col+2];
      o.w = acc[i][j4*4+3] + bias[col+3];
      *(float4*)(C + (size_t)row*ldc + coff + col) = o;
    }
  }
}

// ---------------- centroid selection (key(1) gumbel over NC=2) --------------
__global__ void centroid_select(const float* __restrict__ cent) {
  int idx = blockIdx.x * blockDim.x + threadIdx.x;
  if (idx >= BDIM*SDIM*NH) return;
  int b = idx / (SDIM*NH);
  int r = idx - b*(SDIM*NH);
  int s = r / NH;
  int h = r - s*NH;
  const float* kk = d_QKV + (size_t)(b*SDIM + s)*QKVLD + HDIM + h*HD;
  float l0 = 0.f, l1 = 0.f;
#pragma unroll
  for (int d = 0; d < HD; d++) {
    float kv = kk[d];
    l0 += kv * cent[2*d];
    l1 += kv * cent[2*d + 1];
  }
  unsigned base = 2u * (unsigned)idx;  // flat index into [B,S,NH,NC]
  float g0 = gumbel_of_u(u_from_v23(tf_bits(0u, 1u, base)      >> 9));
  float g1 = gumbel_of_u(u_from_v23(tf_bits(0u, 1u, base + 1u) >> 9));
  // argmax over 2 (first index on tie, matching jnp.argmax)
  int c = ((l1 + g1) > (l0 + g0)) ? 1 : 0;
  d_code[((b*NH + h) << 10) + s] = (unsigned char)c;
}

// ---------------- attention selection (key(2) gumbel over S=1024) -----------
// One warp per (b,h,q) row. Within a centroid group all logits are equal, so
// the within-group argmax is bitwise: pack (u23<<10)|(1023-k) -> max packed =
// max u, smallest k on tie (matching jnp.argmax first-index tie-break).
__device__ __forceinline__ int pick_k(unsigned long long b0, unsigned long long b1,
                                      float D0, float D1) {
  int k0 = 1023 - (int)(b0 & 1023u);
  int k1 = 1023 - (int)(b1 & 1023u);
  float s0 = D0 + gumbel_of_u(u_from_v23((unsigned)(b0 >> 10)));
  float s1 = D1 + gumbel_of_u(u_from_v23((unsigned)(b1 >> 10)));
  if (s0 > s1) return k0;
  if (s1 > s0) return k1;
  return min(k0, k1);
}

__global__ __launch_bounds__(256) void attn_select(const float* __restrict__ cent) {
  int gw = (blockIdx.x * blockDim.x + threadIdx.x) >> 5;  // row id
  int lane = threadIdx.x & 31;
  if (gw >= NROWSEL) return;
  int bh = gw >> 10, q = gw & 1023;
  int b = bh / NH, h = bh - b*NH;

  const float* qp = d_QKV + (size_t)(b*SDIM + q)*QKVLD + h*HD;
  float p0 = 0.f, p1 = 0.f;
#pragma unroll
  for (int d = lane; d < HD; d += 32) {
    float a = qp[d];
    p0 += a * cent[2*d];
    p1 += a * cent[2*d + 1];
  }
#pragma unroll
  for (int o = 16; o; o >>= 1) {
    p0 += __shfl_xor_sync(0xffffffffu, p0, o);
    p1 += __shfl_xor_sync(0xffffffffu, p1, o);
  }
  const unsigned char* cd = d_code + ((size_t)bh << 10);
  unsigned long long best0 = 0ull, best1 = 0ull;
  unsigned base = (unsigned)gw * 1024u;  // flat index into [B,NH,S,S]
#pragma unroll 4
  for (int k = lane; k < 1024; k += 32) {
    unsigned bits = tf_bits(0u, 2u, base + (unsigned)k);
    unsigned long long p = (((unsigned long long)(bits >> 9)) << 10) | (unsigned)(1023 - k);
    if (cd[k]) { if (p > best1) best1 = p; } else { if (p > best0) best0 = p; }
  }
#pragma unroll
  for (int o = 16; o; o >>= 1) {
    best0 = max(best0, __shfl_xor_sync(0xffffffffu, best0, o));
    best1 = max(best1, __shfl_xor_sync(0xffffffffu, best1, o));
  }
  if (lane == 0) d_kstar[gw] = pick_k(best0, best1, p0, p1);
}

// ---------------- gather selected V rows into contiguous A ------------------
__global__ void gather_v() {
  int t = blockIdx.x * blockDim.x + threadIdx.x;
  if (t >= MROWS*NH*16) return;
  int f  = t & 15;
  int mh = t >> 4;
  int h  = mh % NH;
  int m  = mh / NH;
  int b  = m >> 10, q = m & 1023;
  int ks = d_kstar[((b*NH + h) << 10) + q];
  const float4* src = (const float4*)(d_QKV + (size_t)(b*SDIM + ks)*QKVLD + 2*HDIM + h*HD);
  float4* dst = (float4*)(d_Ag + (size_t)m*HDIM + h*HD);
  dst[f] = src[f];
}

extern "C" void kernel_launch(void* const* d_in, const int* in_sizes, int n_in,
                              void* d_out, int out_size) {
  // Input mapping. Primary: setup_inputs() dict order. Hedge: if d_in[0] is not
  // the activation tensor (unique size 6291456), assume alphabetical name order
  // (Wk, Wp, Wq, Wv, bk, bp, bq, bv, centroid, input).
  int iIn=0,iWq=1,ibq=2,iWk=3,ibk=4,iWv=5,ibv=6,iC=7,iWp=8,ibp=9;
  if (in_sizes[0] != MROWS*HDIM) {
    iWk=0; iWp=1; iWq=2; iWv=3; ibk=4; ibp=5; ibq=6; ibv=7; iC=8; iIn=9;
  }
  const float* x    = (const float*)d_in[iIn];
  const float* Wq   = (const float*)d_in[iWq];
  const float* bq   = (const float*)d_in[ibq];
  const float* Wk   = (const float*)d_in[iWk];
  const float* bk   = (const float*)d_in[ibk];
  const float* Wv   = (const float*)d_in[iWv];
  const float* bv   = (const float*)d_in[ibv];
  const float* cent = (const float*)d_in[iC];
  const float* Wp   = (const float*)d_in[iWp];
  const float* bp   = (const float*)d_in[ibp];
  float* out = (float*)d_out;

  float *qkv, *ag;
  cudaGetSymbolAddress((void**)&qkv, d_QKV);
  cudaGetSymbolAddress((void**)&ag, d_Ag);

  dim3 grd(HDIM/128, MROWS/128);
  dim3 blk(256);
  sgemm_bias<<<grd, blk>>>(x, Wq, bq, qkv, HDIM, HDIM, HDIM, QKVLD, 0);
  sgemm_bias<<<grd, blk>>>(x, Wk, bk, qkv, HDIM, HDIM, HDIM, QKVLD, HDIM);
  sgemm_bias<<<grd, blk>>>(x, Wv, bv, qkv, HDIM, HDIM, HDIM, QKVLD, 2*HDIM);

  centroid_select<<<(BDIM*SDIM*NH)/256, 256>>>(cent);
  attn_select<<<(NROWSEL*32)/256, 256>>>(cent);
  gather_v<<<(MROWS*NH*16)/256, 256>>>();

  sgemm_bias<<<grd, blk>>>(ag, Wp, bp, out, HDIM, HDIM, HDIM, HDIM, 0);
}

// round 4
// speedup vs baseline: 1.0182x; 1.0182x over previous
#include <cuda_runtime.h>
#include <cuda_bf16.h>
#include <math.h>

// Problem constants
#define BDIM 8
#define SDIM 1024
#define HDIM 768
#define NH   12
#define HD   64
#define MROWS (BDIM*SDIM)        // 8192
#define QKVLD 2304               // 3*HDIM
#define NROWSEL (BDIM*NH*SDIM)   // 98304 rows (b,h,q)
#define TINYF 1.17549435e-38f

// Scratch (allocation-free rule: __device__ globals)
__device__ float d_QKV[MROWS * QKVLD];          // [8192, 2304] = q|k|v
__device__ float d_Ag[MROWS * HDIM];            // gathered V rows
__device__ unsigned char d_code[BDIM*NH*SDIM];  // centroid code, layout [b,h,s]
__device__ int d_kstar[BDIM*NH*SDIM];           // selected key per (b,h,q)

// ---------------- packed f32x2 helpers (Blackwell FFMA2) ----------------
__device__ __forceinline__ void fma2(unsigned long long &d,
                                     unsigned long long a,
                                     unsigned long long b) {
  asm("fma.rn.f32x2 %0, %1, %2, %0;" : "+l"(d) : "l"(a), "l"(b));
}
__device__ __forceinline__ unsigned long long dup2(float x) {
  unsigned long long r;
  asm("mov.b64 %0, {%1, %1};" : "=l"(r) : "r"(__float_as_uint(x)));
  return r;
}
__device__ __forceinline__ void unpack2(unsigned long long v, float &lo, float &hi) {
  unsigned a, b;
  asm("mov.b64 {%0, %1}, %2;" : "=r"(a), "=r"(b) : "l"(v));
  lo = __uint_as_float(a); hi = __uint_as_float(b);
}

// ---------------- JAX threefry2x32 (20 rounds) ----------------
// Verified against Random123 KAT: key(0,0) ctr(0,0) -> (0x6b200159, 0x99ba4efe)
__device__ __forceinline__ void threefry(unsigned k0, unsigned k1,
                                         unsigned &x0, unsigned &x1) {
  unsigned k2 = k0 ^ k1 ^ 0x1BD11BDAu;
  x0 += k0; x1 += k1;
#define TF_R(r) { x0 += x1; x1 = __funnelshift_l(x1, x1, r); x1 ^= x0; }
  TF_R(13) TF_R(15) TF_R(26) TF_R(6)
  x0 += k1; x1 += k2 + 1u;
  TF_R(17) TF_R(29) TF_R(16) TF_R(24)
  x0 += k2; x1 += k0 + 2u;
  TF_R(13) TF_R(15) TF_R(26) TF_R(6)
  x0 += k0; x1 += k1 + 3u;
  TF_R(17) TF_R(29) TF_R(16) TF_R(24)
  x0 += k1; x1 += k2 + 4u;
  TF_R(13) TF_R(15) TF_R(26) TF_R(6)
  x0 += k2; x1 += k0 + 5u;
#undef TF_R
}

// jax_threefry_partitionable=True (default since jax 0.5) 32-bit random bits:
// ctr64 = flat index i (< 2^32 here -> hi word 0), bits = out0 ^ out1.
__device__ __forceinline__ unsigned tf_bits(unsigned k0, unsigned k1, unsigned lo) {
  unsigned x0 = 0u, x1 = lo;
  threefry(k0, k1, x0, x1);
  return x0 ^ x1;
}

// u in [tiny, 1) exactly as jax.random.uniform(minval=tiny, maxval=1)
__device__ __forceinline__ float u_from_v23(unsigned v23) {
  float f = __uint_as_float(v23 | 0x3f800000u) - 1.0f;
  return fmaxf(f, TINYF);
}
__device__ __forceinline__ float gumbel_of_u(float u) {
  // double-precision path -> correctly rounded f32 gumbel
  return (float)(-log(-log((double)u)));
}

// ---------------- SGEMM (FFMA2 f32x2, 128x128x8, bias, col-offset) ----------
__global__ __launch_bounds__(256) void sgemm_bias(
    const float* __restrict__ A, const float* __restrict__ B,
    const float* __restrict__ bias, float* __restrict__ C,
    int K, int lda, int ldb, int ldc, int coff)
{
  __shared__ float As[8][128];
  __shared__ float Bs[8][128];
  int tid = threadIdx.x;
  int bm = blockIdx.y, bn = blockIdx.x;
  int tx = tid & 15, ty = tid >> 4;
  int arow = tid >> 1, acol = (tid & 1) * 4;
  int brow = tid >> 5, bcol = (tid & 31) * 4;

  // acc2[i][j] = packed pair of output cols (tx*8+2j, tx*8+2j+1) for row i
  unsigned long long acc2[8][4];
#pragma unroll
  for (int i = 0; i < 8; i++)
#pragma unroll
    for (int j = 0; j < 4; j++) acc2[i][j] = 0ull;

  for (int k0 = 0; k0 < K; k0 += 8) {
    float4 av = *(const float4*)(A + (size_t)(bm*128 + arow)*lda + k0 + acol);
    float4 bv = *(const float4*)(B + (size_t)(k0 + brow)*ldb + bn*128 + bcol);
    __syncthreads();
    As[acol+0][arow] = av.x;
    As[acol+1][arow] = av.y;
    As[acol+2][arow] = av.z;
    As[acol+3][arow] = av.w;
    *(float4*)&Bs[brow][bcol] = bv;
    __syncthreads();
#pragma unroll
    for (int kk = 0; kk < 8; kk++) {
      float4 a0 = *(const float4*)&As[kk][ty*8];
      float4 a1 = *(const float4*)&As[kk][ty*8+4];
      // consecutive B floats load directly as packed 64-bit pairs
      const unsigned long long* bp = (const unsigned long long*)&Bs[kk][tx*8];
      unsigned long long b2[4] = {bp[0], bp[1], bp[2], bp[3]};
      unsigned long long ad[8] = {dup2(a0.x), dup2(a0.y), dup2(a0.z), dup2(a0.w),
                                  dup2(a1.x), dup2(a1.y), dup2(a1.z), dup2(a1.w)};
#pragma unroll
      for (int i = 0; i < 8; i++)
#pragma unroll
        for (int j = 0; j < 4; j++) fma2(acc2[i][j], ad[i], b2[j]);
    }
  }
#pragma unroll
  for (int i = 0; i < 8; i++) {
    int row = bm*128 + ty*8 + i;
#pragma unroll
    for (int j4 = 0; j4 < 2; j4++) {
      int col = bn*128 + tx*8 + j4*4;
      float l0, h0, l1, h1;
      unpack2(acc2[i][2*j4+0], l0, h0);
      unpack2(acc2[i][2*j4+1], l1, h1);
      float4 o;
      o.x = l0 + bias[col+0];
      o.y = h0 + bias[col+1];
      o.z = l1 + bias[col+2];
      o.w = h1 + bias[col+3];
      *(float4*)(C + (size_t)row*ldc + coff + col) = o;
    }
  }
}

// ---------------- centroid selection (key(1) gumbel over NC=2) --------------
__global__ void centroid_select(const float* __restrict__ cent) {
  int idx = blockIdx.x * blockDim.x + threadIdx.x;
  if (idx >= BDIM*SDIM*NH) return;
  int b = idx / (SDIM*NH);
  int r = idx - b*(SDIM*NH);
  int s = r / NH;
  int h = r - s*NH;
  const float* kk = d_QKV + (size_t)(b*SDIM + s)*QKVLD + HDIM + h*HD;
  float l0 = 0.f, l1 = 0.f;
#pragma unroll
  for (int d = 0; d < HD; d++) {
    float kv = kk[d];
    l0 += kv * cent[2*d];
    l1 += kv * cent[2*d + 1];
  }
  unsigned base = 2u * (unsigned)idx;  // flat index into [B,S,NH,NC]
  float g0 = gumbel_of_u(u_from_v23(tf_bits(0u, 1u, base)      >> 9));
  float g1 = gumbel_of_u(u_from_v23(tf_bits(0u, 1u, base + 1u) >> 9));
  // argmax over 2 (first index on tie, matching jnp.argmax)
  int c = ((l1 + g1) > (l0 + g0)) ? 1 : 0;
  d_code[((b*NH + h) << 10) + s] = (unsigned char)c;
}

// ---------------- attention selection (key(2) gumbel over S=1024) -----------
// One warp per (b,h,q) row. Within a centroid group all logits are equal, so
// the within-group argmax is bitwise: pack (u23<<10)|(1023-k) -> max packed =
// max u, smallest k on tie (matching jnp.argmax first-index tie-break).
__device__ __forceinline__ int pick_k(unsigned long long b0, unsigned long long b1,
                                      float D0, float D1) {
  int k0 = 1023 - (int)(b0 & 1023u);
  int k1 = 1023 - (int)(b1 & 1023u);
  float s0 = D0 + gumbel_of_u(u_from_v23((unsigned)(b0 >> 10)));
  float s1 = D1 + gumbel_of_u(u_from_v23((unsigned)(b1 >> 10)));
  if (s0 > s1) return k0;
  if (s1 > s0) return k1;
  return min(k0, k1);
}

__global__ __launch_bounds__(256) void attn_select(const float* __restrict__ cent) {
  int gw = (blockIdx.x * blockDim.x + threadIdx.x) >> 5;  // row id
  int lane = threadIdx.x & 31;
  if (gw >= NROWSEL) return;
  int bh = gw >> 10, q = gw & 1023;
  int b = bh / NH, h = bh - b*NH;

  const float* qp = d_QKV + (size_t)(b*SDIM + q)*QKVLD + h*HD;
  float p0 = 0.f, p1 = 0.f;
#pragma unroll
  for (int d = lane; d < HD; d += 32) {
    float a = qp[d];
    p0 += a * cent[2*d];
    p1 += a * cent[2*d + 1];
  }
#pragma unroll
  for (int o = 16; o; o >>= 1) {
    p0 += __shfl_xor_sync(0xffffffffu, p0, o);
    p1 += __shfl_xor_sync(0xffffffffu, p1, o);
  }
  const unsigned char* cd = d_code + ((size_t)bh << 10);
  unsigned long long best0 = 0ull, best1 = 0ull;
  unsigned base = (unsigned)gw * 1024u;  // flat index into [B,NH,S,S]
#pragma unroll 4
  for (int k = lane; k < 1024; k += 32) {
    unsigned bits = tf_bits(0u, 2u, base + (unsigned)k);
    unsigned long long p = (((unsigned long long)(bits >> 9)) << 10) | (unsigned)(1023 - k);
    if (cd[k]) { if (p > best1) best1 = p; } else { if (p > best0) best0 = p; }
  }
#pragma unroll
  for (int o = 16; o; o >>= 1) {
    best0 = max(best0, __shfl_xor_sync(0xffffffffu, best0, o));
    best1 = max(best1, __shfl_xor_sync(0xffffffffu, best1, o));
  }
  if (lane == 0) d_kstar[gw] = pick_k(best0, best1, p0, p1);
}

// ---------------- gather selected V rows into contiguous A ------------------
__global__ void gather_v() {
  int t = blockIdx.x * blockDim.x + threadIdx.x;
  if (t >= MROWS*NH*16) return;
  int f  = t & 15;
  int mh = t >> 4;
  int h  = mh % NH;
  int m  = mh / NH;
  int b  = m >> 10, q = m & 1023;
  int ks = d_kstar[((b*NH + h) << 10) + q];
  const float4* src = (const float4*)(d_QKV + (size_t)(b*SDIM + ks)*QKVLD + 2*HDIM + h*HD);
  float4* dst = (float4*)(d_Ag + (size_t)m*HDIM + h*HD);
  dst[f] = src[f];
}

extern "C" void kernel_launch(void* const* d_in, const int* in_sizes, int n_in,
                              void* d_out, int out_size) {
  // Input mapping. Primary: setup_inputs() dict order. Hedge: if d_in[0] is not
  // the activation tensor (unique size 6291456), assume alphabetical name order
  // (Wk, Wp, Wq, Wv, bk, bp, bq, bv, centroid, input).
  int iIn=0,iWq=1,ibq=2,iWk=3,ibk=4,iWv=5,ibv=6,iC=7,iWp=8,ibp=9;
  if (in_sizes[0] != MROWS*HDIM) {
    iWk=0; iWp=1; iWq=2; iWv=3; ibk=4; ibp=5; ibq=6; ibv=7; iC=8; iIn=9;
  }
  const float* x    = (const float*)d_in[iIn];
  const float* Wq   = (const float*)d_in[iWq];
  const float* bq   = (const float*)d_in[ibq];
  const float* Wk   = (const float*)d_in[iWk];
  const float* bk   = (const float*)d_in[ibk];
  const float* Wv   = (const float*)d_in[iWv];
  const float* bv   = (const float*)d_in[ibv];
  const float* cent = (const float*)d_in[iC];
  const float* Wp   = (const float*)d_in[iWp];
  const float* bp   = (const float*)d_in[ibp];
  float* out = (float*)d_out;

  float *qkv, *ag;
  cudaGetSymbolAddress((void**)&qkv, d_QKV);
  cudaGetSymbolAddress((void**)&ag, d_Ag);

  dim3 grd(HDIM/128, MROWS/128);
  dim3 blk(256);
  sgemm_bias<<<grd, blk>>>(x, Wq, bq, qkv, HDIM, HDIM, HDIM, QKVLD, 0);
  sgemm_bias<<<grd, blk>>>(x, Wk, bk, qkv, HDIM, HDIM, HDIM, QKVLD, HDIM);
  sgemm_bias<<<grd, blk>>>(x, Wv, bv, qkv, HDIM, HDIM, HDIM, QKVLD, 2*HDIM);

  centroid_select<<<(BDIM*SDIM*NH)/256, 256>>>(cent);
  attn_select<<<(NROWSEL*32)/256, 256>>>(cent);
  gather_v<<<(MROWS*NH*16)/256, 256>>>();

  sgemm_bias<<<grd, blk>>>(ag, Wp, bp, out, HDIM, HDIM, HDIM, HDIM, 0);
}

// round 5
// speedup vs baseline: 1.3724x; 1.3479x over previous
#include <cuda_runtime.h>
#include <cuda_bf16.h>
#include <math.h>

// Problem constants
#define BDIM 8
#define SDIM 1024
#define HDIM 768
#define NH   12
#define HD   64
#define MROWS (BDIM*SDIM)        // 8192
#define NROWSEL (BDIM*NH*SDIM)   // 98304 rows (b,h,q)
#define NCOL 48                  // 24 q-logit cols | 24 k-logit cols
#define TINYF 1.17549435e-38f

// Scratch (allocation-free rule: __device__ globals)
__device__ float d_V[MROWS * HDIM];             // V = x@Wv + bv
__device__ float d_Ag[MROWS * HDIM];            // gathered V rows
__device__ float d_Wc[HDIM * NCOL];             // folded weights [768][48] (q|k)
__device__ float d_bc[NCOL];                    // folded biases
__device__ float d_L[MROWS * NCOL];             // logits [8192][48] (q|k)
__device__ unsigned char d_code[BDIM*NH*SDIM];  // centroid code, layout [b,h,s]
__device__ int d_kstar[BDIM*NH*SDIM];           // selected key per (b,h,q)

// ---------------- packed f32x2 helpers (Blackwell FFMA2) ----------------
__device__ __forceinline__ void fma2(unsigned long long &d,
                                     unsigned long long a,
                                     unsigned long long b) {
  asm("fma.rn.f32x2 %0, %1, %2, %0;" : "+l"(d) : "l"(a), "l"(b));
}
__device__ __forceinline__ unsigned long long dup2(float x) {
  unsigned long long r;
  asm("mov.b64 %0, {%1, %1};" : "=l"(r) : "r"(__float_as_uint(x)));
  return r;
}
__device__ __forceinline__ void unpack2(unsigned long long v, float &lo, float &hi) {
  unsigned a, b;
  asm("mov.b64 {%0, %1}, %2;" : "=r"(a), "=r"(b) : "l"(v));
  lo = __uint_as_float(a); hi = __uint_as_float(b);
}

// ---------------- JAX threefry2x32 (20 rounds) ----------------
__device__ __forceinline__ void threefry(unsigned k0, unsigned k1,
                                         unsigned &x0, unsigned &x1) {
  unsigned k2 = k0 ^ k1 ^ 0x1BD11BDAu;
  x0 += k0; x1 += k1;
#define TF_R(r) { x0 += x1; x1 = __funnelshift_l(x1, x1, r); x1 ^= x0; }
  TF_R(13) TF_R(15) TF_R(26) TF_R(6)
  x0 += k1; x1 += k2 + 1u;
  TF_R(17) TF_R(29) TF_R(16) TF_R(24)
  x0 += k2; x1 += k0 + 2u;
  TF_R(13) TF_R(15) TF_R(26) TF_R(6)
  x0 += k0; x1 += k1 + 3u;
  TF_R(17) TF_R(29) TF_R(16) TF_R(24)
  x0 += k1; x1 += k2 + 4u;
  TF_R(13) TF_R(15) TF_R(26) TF_R(6)
  x0 += k2; x1 += k0 + 5u;
#undef TF_R
}

// jax_threefry_partitionable counter-mode bits: ctr=(0,i), bits = x0^x1
__device__ __forceinline__ unsigned tf_bits(unsigned k0, unsigned k1, unsigned lo) {
  unsigned x0 = 0u, x1 = lo;
  threefry(k0, k1, x0, x1);
  return x0 ^ x1;
}

__device__ __forceinline__ float u_from_v23(unsigned v23) {
  float f = __uint_as_float(v23 | 0x3f800000u) - 1.0f;
  return fmaxf(f, TINYF);
}
__device__ __forceinline__ float gumbel_of_u(float u) {
  return (float)(-log(-log((double)u)));
}

// ---------------- fold: Wc = [Wq@Cblk | Wk@Cblk], bc likewise ---------------
__global__ void prep_wc(const float* __restrict__ Wq, const float* __restrict__ Wk,
                        const float* __restrict__ bq, const float* __restrict__ bk,
                        const float* __restrict__ cent) {
  int t = blockIdx.x * blockDim.x + threadIdx.x;
  if (t < HDIM * NCOL) {
    int row = t / NCOL, j = t - row * NCOL;
    const float* W = (j < 24) ? Wq : Wk;
    int h = (j % 24) >> 1, c = j & 1;
    float s = 0.f;
#pragma unroll
    for (int d = 0; d < HD; d++)
      s += W[row * HDIM + h * HD + d] * cent[d * 2 + c];
    d_Wc[row * NCOL + j] = s;
  } else if (t < HDIM * NCOL + NCOL) {
    int j = t - HDIM * NCOL;
    const float* bb = (j < 24) ? bq : bk;
    int h = (j % 24) >> 1, c = j & 1;
    float s = 0.f;
#pragma unroll
    for (int d = 0; d < HD; d++)
      s += bb[h * HD + d] * cent[d * 2 + c];
    d_bc[j] = s;
  }
}

// ---------------- thin GEMM: L[8192,48] = x @ Wc + bc -----------------------
// block: 128 rows x 48 cols, 256 threads (thread: row r=tid&127, colgrp g=tid>>7)
__global__ __launch_bounds__(256) void logits_x(const float* __restrict__ x) {
  __shared__ float Xs[128][65];   // padded: conflict-free column reads
  __shared__ float Ws[64][NCOL];
  int tid = threadIdx.x;
  int row0 = blockIdx.x * 128;
  int r = tid & 127, g = tid >> 7;

  float acc[24];
#pragma unroll
  for (int j = 0; j < 24; j++) acc[j] = 0.f;

  for (int k0 = 0; k0 < HDIM; k0 += 64) {
    __syncthreads();
#pragma unroll
    for (int i = 0; i < 8; i++) {          // 2048 float4 / 256 threads
      int f4 = tid + i * 256;
      int fr = f4 >> 4, fc = (f4 & 15) * 4;
      float4 v = *(const float4*)(x + (size_t)(row0 + fr) * HDIM + k0 + fc);
      Xs[fr][fc+0] = v.x; Xs[fr][fc+1] = v.y; Xs[fr][fc+2] = v.z; Xs[fr][fc+3] = v.w;
    }
#pragma unroll
    for (int i = 0; i < 3; i++) {          // 768 float4 / 256 threads
      int f4 = tid + i * 256;
      int wr = f4 / 12, wc = (f4 % 12) * 4;
      *(float4*)&Ws[wr][wc] = *(const float4*)(d_Wc + (size_t)(k0 + wr) * NCOL + wc);
    }
    __syncthreads();
#pragma unroll 4
    for (int kk = 0; kk < 64; kk++) {
      float xv = Xs[r][kk];
      const float4* w4 = (const float4*)&Ws[kk][g * 24];
#pragma unroll
      for (int q4 = 0; q4 < 6; q4++) {
        float4 w = w4[q4];
        acc[q4*4+0] += xv * w.x;
        acc[q4*4+1] += xv * w.y;
        acc[q4*4+2] += xv * w.z;
        acc[q4*4+3] += xv * w.w;
      }
    }
  }
  float* Lp = d_L + (size_t)(row0 + r) * NCOL + g * 24;
#pragma unroll
  for (int q4 = 0; q4 < 6; q4++) {
    float4 o;
    o.x = acc[q4*4+0] + d_bc[g*24 + q4*4+0];
    o.y = acc[q4*4+1] + d_bc[g*24 + q4*4+1];
    o.z = acc[q4*4+2] + d_bc[g*24 + q4*4+2];
    o.w = acc[q4*4+3] + d_bc[g*24 + q4*4+3];
    *(float4*)(Lp + q4*4) = o;
  }
}

// ---------------- SGEMM (FFMA2 f32x2, 128x128x8, bias) ----------------------
__global__ __launch_bounds__(256) void sgemm_bias(
    const float* __restrict__ A, const float* __restrict__ B,
    const float* __restrict__ bias, float* __restrict__ C,
    int K, int lda, int ldb, int ldc)
{
  __shared__ float As[8][128];
  __shared__ float Bs[8][128];
  int tid = threadIdx.x;
  int bm = blockIdx.y, bn = blockIdx.x;
  int tx = tid & 15, ty = tid >> 4;
  int arow = tid >> 1, acol = (tid & 1) * 4;
  int brow = tid >> 5, bcol = (tid & 31) * 4;

  unsigned long long acc2[8][4];
#pragma unroll
  for (int i = 0; i < 8; i++)
#pragma unroll
    for (int j = 0; j < 4; j++) acc2[i][j] = 0ull;

  for (int k0 = 0; k0 < K; k0 += 8) {
    float4 av = *(const float4*)(A + (size_t)(bm*128 + arow)*lda + k0 + acol);
    float4 bv = *(const float4*)(B + (size_t)(k0 + brow)*ldb + bn*128 + bcol);
    __syncthreads();
    As[acol+0][arow] = av.x;
    As[acol+1][arow] = av.y;
    As[acol+2][arow] = av.z;
    As[acol+3][arow] = av.w;
    *(float4*)&Bs[brow][bcol] = bv;
    __syncthreads();
#pragma unroll
    for (int kk = 0; kk < 8; kk++) {
      float4 a0 = *(const float4*)&As[kk][ty*8];
      float4 a1 = *(const float4*)&As[kk][ty*8+4];
      const unsigned long long* bp = (const unsigned long long*)&Bs[kk][tx*8];
      unsigned long long b2[4] = {bp[0], bp[1], bp[2], bp[3]};
      unsigned long long ad[8] = {dup2(a0.x), dup2(a0.y), dup2(a0.z), dup2(a0.w),
                                  dup2(a1.x), dup2(a1.y), dup2(a1.z), dup2(a1.w)};
#pragma unroll
      for (int i = 0; i < 8; i++)
#pragma unroll
        for (int j = 0; j < 4; j++) fma2(acc2[i][j], ad[i], b2[j]);
    }
  }
#pragma unroll
  for (int i = 0; i < 8; i++) {
    int row = bm*128 + ty*8 + i;
#pragma unroll
    for (int j4 = 0; j4 < 2; j4++) {
      int col = bn*128 + tx*8 + j4*4;
      float l0, h0, l1, h1;
      unpack2(acc2[i][2*j4+0], l0, h0);
      unpack2(acc2[i][2*j4+1], l1, h1);
      float4 o;
      o.x = l0 + bias[col+0];
      o.y = h0 + bias[col+1];
      o.z = l1 + bias[col+2];
      o.w = h1 + bias[col+3];
      *(float4*)(C + (size_t)row*ldc + col) = o;
    }
  }
}

// ---------------- centroid selection (key(1) gumbel over NC=2) --------------
__global__ void centroid_select() {
  int idx = blockIdx.x * blockDim.x + threadIdx.x;  // flat (b,s,h)
  if (idx >= BDIM*SDIM*NH) return;
  int b = idx / (SDIM*NH);
  int r = idx - b*(SDIM*NH);
  int s = r / NH;
  int h = r - s*NH;
  const float* Lk = d_L + (size_t)(b*SDIM + s) * NCOL + 24 + h*2;
  float l0 = Lk[0], l1 = Lk[1];
  unsigned base = 2u * (unsigned)idx;  // flat index into [B,S,NH,NC]
  float g0 = gumbel_of_u(u_from_v23(tf_bits(0u, 1u, base)      >> 9));
  float g1 = gumbel_of_u(u_from_v23(tf_bits(0u, 1u, base + 1u) >> 9));
  int c = ((l1 + g1) > (l0 + g0)) ? 1 : 0;
  d_code[((b*NH + h) << 10) + s] = (unsigned char)c;
}

// ---------------- attention selection (key(2) gumbel over S=1024) -----------
__device__ __forceinline__ int pick_k(unsigned long long b0, unsigned long long b1,
                                      float D0, float D1) {
  int k0 = 1023 - (int)(b0 & 1023u);
  int k1 = 1023 - (int)(b1 & 1023u);
  float s0 = D0 + gumbel_of_u(u_from_v23((unsigned)(b0 >> 10)));
  float s1 = D1 + gumbel_of_u(u_from_v23((unsigned)(b1 >> 10)));
  if (s0 > s1) return k0;
  if (s1 > s0) return k1;
  return min(k0, k1);
}

__global__ __launch_bounds__(256) void attn_select() {
  int gw = (blockIdx.x * blockDim.x + threadIdx.x) >> 5;  // row id (b,h,q)
  int lane = threadIdx.x & 31;
  if (gw >= NROWSEL) return;
  int bh = gw >> 10, q = gw & 1023;
  int b = bh / NH, h = bh - b*NH;

  const float* Lq = d_L + (size_t)(b*SDIM + q) * NCOL + h*2;
  float p0 = Lq[0], p1 = Lq[1];

  const unsigned char* cd = d_code + ((size_t)bh << 10);
  unsigned long long best0 = 0ull, best1 = 0ull;
  unsigned base = (unsigned)gw * 1024u;  // flat index into [B,NH,S,S]
#pragma unroll 4
  for (int k = lane; k < 1024; k += 32) {
    unsigned bits = tf_bits(0u, 2u, base + (unsigned)k);
    unsigned long long p = (((unsigned long long)(bits >> 9)) << 10) | (unsigned)(1023 - k);
    if (cd[k]) { if (p > best1) best1 = p; } else { if (p > best0) best0 = p; }
  }
#pragma unroll
  for (int o = 16; o; o >>= 1) {
    best0 = max(best0, __shfl_xor_sync(0xffffffffu, best0, o));
    best1 = max(best1, __shfl_xor_sync(0xffffffffu, best1, o));
  }
  if (lane == 0) d_kstar[gw] = pick_k(best0, best1, p0, p1);
}

// ---------------- gather selected V rows into contiguous A ------------------
__global__ void gather_v() {
  int t = blockIdx.x * blockDim.x + threadIdx.x;
  if (t >= MROWS*NH*16) return;
  int f  = t & 15;
  int mh = t >> 4;
  int h  = mh % NH;
  int m  = mh / NH;
  int b  = m >> 10, q = m & 1023;
  int ks = d_kstar[((b*NH + h) << 10) + q];
  const float4* src = (const float4*)(d_V + (size_t)(b*SDIM + ks)*HDIM + h*HD);
  float4* dst = (float4*)(d_Ag + (size_t)m*HDIM + h*HD);
  dst[f] = src[f];
}

extern "C" void kernel_launch(void* const* d_in, const int* in_sizes, int n_in,
                              void* d_out, int out_size) {
  // Input mapping. Primary: setup_inputs() dict order. Hedge: alphabetical.
  int iIn=0,iWq=1,ibq=2,iWk=3,ibk=4,iWv=5,ibv=6,iC=7,iWp=8,ibp=9;
  if (in_sizes[0] != MROWS*HDIM) {
    iWk=0; iWp=1; iWq=2; iWv=3; ibk=4; ibp=5; ibq=6; ibv=7; iC=8; iIn=9;
  }
  const float* x    = (const float*)d_in[iIn];
  const float* Wq   = (const float*)d_in[iWq];
  const float* bq   = (const float*)d_in[ibq];
  const float* Wk   = (const float*)d_in[iWk];
  const float* bk   = (const float*)d_in[ibk];
  const float* Wv   = (const float*)d_in[iWv];
  const float* bv   = (const float*)d_in[ibv];
  const float* cent = (const float*)d_in[iC];
  const float* Wp   = (const float*)d_in[iWp];
  const float* bp   = (const float*)d_in[ibp];
  float* out = (float*)d_out;

  float *vbuf, *ag;
  cudaGetSymbolAddress((void**)&vbuf, d_V);
  cudaGetSymbolAddress((void**)&ag, d_Ag);

  // Fold Wq/Wk through centroids, then thin logits GEMM
  prep_wc<<<(HDIM*NCOL + NCOL + 255)/256, 256>>>(Wq, Wk, bq, bk, cent);
  logits_x<<<MROWS/128, 256>>>(x);

  // V projection (full GEMM)
  dim3 grd(HDIM/128, MROWS/128);
  sgemm_bias<<<grd, 256>>>(x, Wv, bv, vbuf, HDIM, HDIM, HDIM, HDIM);

  centroid_select<<<(BDIM*SDIM*NH)/256, 256>>>();
  attn_select<<<(NROWSEL*32)/256, 256>>>();
  gather_v<<<(MROWS*NH*16)/256, 256>>>();

  sgemm_bias<<<grd, 256>>>(ag, Wp, bp, out, HDIM, HDIM, HDIM, HDIM);
}

// round 7
// speedup vs baseline: 1.7058x; 1.2429x over previous
#include <cuda_runtime.h>
#include <cuda_bf16.h>
#include <cstdint>
#include <math.h>

// Problem constants
#define BDIM 8
#define SDIM 1024
#define HDIM 768
#define NH   12
#define HD   64
#define MROWS (BDIM*SDIM)        // 8192
#define NROWSEL (BDIM*NH*SDIM)   // 98304 rows (b,h,q)
#define NCOL 48                  // 24 q-logit cols | 24 k-logit cols
#define KP   2304                // split-K: [hi|hi|lo] x [hi|lo|hi]
#define KCH  72                  // KP/32 k-chunks
#define TINYF 1.17549435e-38f

// Scratch (allocation-free rule: __device__ globals)
__device__ float d_V[MROWS * HDIM];             // V = x@Wv + bv (f32)
__device__ float d_Wc[HDIM * NCOL];             // folded logit weights
__device__ float d_bc[NCOL];
__device__ float d_L[MROWS * NCOL];             // logits [8192][48] (q|k)
__device__ unsigned char d_code[BDIM*NH*SDIM];
__device__ int d_kstar[BDIM*NH*SDIM];
// split-bf16 GEMM operands (K-folded 3-product layout)
__device__ __nv_bfloat16 d_Ap[MROWS * KP];      // x:  [Ah | Ah | Al]
__device__ __nv_bfloat16 d_Agp[MROWS * KP];     // gathered V, same layout
__device__ __nv_bfloat16 d_Bv[HDIM * KP];       // WvT: [Bh | Bl | Bh]
__device__ __nv_bfloat16 d_Bw[HDIM * KP];       // WpT: [Bh | Bl | Bh]

__device__ __forceinline__ uint32_t smem_u32(const void* p) {
  uint32_t a;
  asm("{ .reg .u64 t; cvta.to.shared.u64 t, %1; cvt.u32.u64 %0, t; }" : "=r"(a) : "l"(p));
  return a;
}

// ======================= JAX threefry2x32 =======================
__device__ __forceinline__ void threefry(unsigned k0, unsigned k1,
                                         unsigned &x0, unsigned &x1) {
  unsigned k2 = k0 ^ k1 ^ 0x1BD11BDAu;
  x0 += k0; x1 += k1;
#define TF_R(r) { x0 += x1; x1 = __funnelshift_l(x1, x1, r); x1 ^= x0; }
  TF_R(13) TF_R(15) TF_R(26) TF_R(6)
  x0 += k1; x1 += k2 + 1u;
  TF_R(17) TF_R(29) TF_R(16) TF_R(24)
  x0 += k2; x1 += k0 + 2u;
  TF_R(13) TF_R(15) TF_R(26) TF_R(6)
  x0 += k0; x1 += k1 + 3u;
  TF_R(17) TF_R(29) TF_R(16) TF_R(24)
  x0 += k1; x1 += k2 + 4u;
  TF_R(13) TF_R(15) TF_R(26) TF_R(6)
  x0 += k2; x1 += k0 + 5u;
#undef TF_R
}
__device__ __forceinline__ unsigned tf_bits(unsigned k0, unsigned k1, unsigned lo) {
  unsigned x0 = 0u, x1 = lo;
  threefry(k0, k1, x0, x1);
  return x0 ^ x1;
}
__device__ __forceinline__ float u_from_v23(unsigned v23) {
  float f = __uint_as_float(v23 | 0x3f800000u) - 1.0f;
  return fmaxf(f, TINYF);
}
__device__ __forceinline__ float gumbel_of_u(float u) {
  return (float)(-log(-log((double)u)));
}

// ============ fold: Wc = [Wq@Cblk | Wk@Cblk], bc likewise ============
__global__ void prep_wc(const float* __restrict__ Wq, const float* __restrict__ Wk,
                        const float* __restrict__ bq, const float* __restrict__ bk,
                        const float* __restrict__ cent) {
  int t = blockIdx.x * blockDim.x + threadIdx.x;
  if (t < HDIM * NCOL) {
    int row = t / NCOL, j = t - row * NCOL;
    const float* W = (j < 24) ? Wq : Wk;
    int h = (j % 24) >> 1, c = j & 1;
    float s = 0.f;
#pragma unroll
    for (int d = 0; d < HD; d++)
      s += W[row * HDIM + h * HD + d] * cent[d * 2 + c];
    d_Wc[row * NCOL + j] = s;
  } else if (t < HDIM * NCOL + NCOL) {
    int j = t - HDIM * NCOL;
    const float* bb = (j < 24) ? bq : bk;
    int h = (j % 24) >> 1, c = j & 1;
    float s = 0.f;
#pragma unroll
    for (int d = 0; d < HD; d++)
      s += bb[h * HD + d] * cent[d * 2 + c];
    d_bc[j] = s;
  }
}

// ============ thin GEMM: L[8192,48] = x @ Wc + bc ============
__global__ __launch_bounds__(256) void logits_x(const float* __restrict__ x) {
  __shared__ float Xs[128][65];
  __shared__ float Ws[64][NCOL];
  int tid = threadIdx.x;
  int row0 = blockIdx.x * 128;
  int r = tid & 127, g = tid >> 7;

  float acc[24];
#pragma unroll
  for (int j = 0; j < 24; j++) acc[j] = 0.f;

  for (int k0 = 0; k0 < HDIM; k0 += 64) {
    __syncthreads();
#pragma unroll
    for (int i = 0; i < 8; i++) {
      int f4 = tid + i * 256;
      int fr = f4 >> 4, fc = (f4 & 15) * 4;
      float4 v = *(const float4*)(x + (size_t)(row0 + fr) * HDIM + k0 + fc);
      Xs[fr][fc+0] = v.x; Xs[fr][fc+1] = v.y; Xs[fr][fc+2] = v.z; Xs[fr][fc+3] = v.w;
    }
#pragma unroll
    for (int i = 0; i < 3; i++) {
      int f4 = tid + i * 256;
      int wr = f4 / 12, wc = (f4 % 12) * 4;
      *(float4*)&Ws[wr][wc] = *(const float4*)(d_Wc + (size_t)(k0 + wr) * NCOL + wc);
    }
    __syncthreads();
#pragma unroll 4
    for (int kk = 0; kk < 64; kk++) {
      float xv = Xs[r][kk];
      const float4* w4 = (const float4*)&Ws[kk][g * 24];
#pragma unroll
      for (int q4 = 0; q4 < 6; q4++) {
        float4 w = w4[q4];
        acc[q4*4+0] += xv * w.x;
        acc[q4*4+1] += xv * w.y;
        acc[q4*4+2] += xv * w.z;
        acc[q4*4+3] += xv * w.w;
      }
    }
  }
  float* Lp = d_L + (size_t)(row0 + r) * NCOL + g * 24;
#pragma unroll
  for (int q4 = 0; q4 < 6; q4++) {
    float4 o;
    o.x = acc[q4*4+0] + d_bc[g*24 + q4*4+0];
    o.y = acc[q4*4+1] + d_bc[g*24 + q4*4+1];
    o.z = acc[q4*4+2] + d_bc[g*24 + q4*4+2];
    o.w = acc[q4*4+3] + d_bc[g*24 + q4*4+3];
    *(float4*)(Lp + q4*4) = o;
  }
}

// ============ split helpers ============
__device__ __forceinline__ void split4(float4 v, uint2 &h, uint2 &l) {
  unsigned short hx = __bfloat16_as_ushort(__float2bfloat16(v.x));
  unsigned short hy = __bfloat16_as_ushort(__float2bfloat16(v.y));
  unsigned short hz = __bfloat16_as_ushort(__float2bfloat16(v.z));
  unsigned short hw = __bfloat16_as_ushort(__float2bfloat16(v.w));
  unsigned short lx = __bfloat16_as_ushort(__float2bfloat16(v.x - __bfloat162float(__ushort_as_bfloat16(hx))));
  unsigned short ly = __bfloat16_as_ushort(__float2bfloat16(v.y - __bfloat162float(__ushort_as_bfloat16(hy))));
  unsigned short lz = __bfloat16_as_ushort(__float2bfloat16(v.z - __bfloat162float(__ushort_as_bfloat16(hz))));
  unsigned short lw = __bfloat16_as_ushort(__float2bfloat16(v.w - __bfloat162float(__ushort_as_bfloat16(hw))));
  h = make_uint2((unsigned)hx | ((unsigned)hy << 16), (unsigned)hz | ((unsigned)hw << 16));
  l = make_uint2((unsigned)lx | ((unsigned)ly << 16), (unsigned)lz | ((unsigned)lw << 16));
}

// x [8192][768] f32 -> d_Ap [8192][2304] = [Ah | Ah | Al]
__global__ void conv_xsplit(const float4* __restrict__ in) {
  int i = blockIdx.x * blockDim.x + threadIdx.x;
  if (i >= MROWS * 192) return;
  int row = i / 192, c4 = (i - row * 192) * 4;
  uint2 h, l;
  split4(in[i], h, l);
  size_t base = (size_t)row * KP + c4;
  *(uint2*)(d_Ap + base)        = h;
  *(uint2*)(d_Ap + base + 768)  = h;
  *(uint2*)(d_Ap + base + 1536) = l;
}

// W [768 k][768 n] f32 -> Bp [768 n][2304] = [Bh | Bl | Bh]
__global__ void conv_wsplit(const float* __restrict__ W, __nv_bfloat16* __restrict__ Bp) {
  int idx = blockIdx.x * blockDim.x + threadIdx.x;
  if (idx >= HDIM * HDIM) return;
  int n = idx / HDIM, k = idx - n * HDIM;
  float v = W[(size_t)k * HDIM + n];
  __nv_bfloat16 hb = __float2bfloat16(v);
  __nv_bfloat16 lb = __float2bfloat16(v - __bfloat162float(hb));
  size_t base = (size_t)n * KP;
  Bp[base + k]        = hb;
  Bp[base + 768 + k]  = lb;
  Bp[base + 1536 + k] = hb;
}

// ============ bf16 mma.sync GEMM: C[8192,768] = A'@B'^T + bias ============
// A' [M][2304] row-major; B' [768][2304] n-major; f32 accum/out.
__global__ __launch_bounds__(256) void mma_gemm(
    const __nv_bfloat16* __restrict__ A, const __nv_bfloat16* __restrict__ B,
    const float* __restrict__ bias, float* __restrict__ C)
{
  __shared__ __nv_bfloat16 As[2][128][40];   // 80B row stride: conflict-free ldmatrix
  __shared__ __nv_bfloat16 Bs[2][128][40];
  int tid = threadIdx.x;
  int wid = tid >> 5, lane = tid & 31;
  int M0 = blockIdx.y * 128, N0 = blockIdx.x * 128;
  int wm = (wid & 1) * 64, wn = (wid >> 1) * 32;

  float acc[4][4][4] = {};

  uint4 pa[2], pb[2];
#define G_LOAD(k0) do { \
    _Pragma("unroll") \
    for (int i = 0; i < 2; i++) { \
      int ch = tid + i * 256; \
      int row = ch >> 2, c16 = (ch & 3) * 8; \
      pa[i] = *(const uint4*)(A + (size_t)(M0 + row) * KP + (k0) + c16); \
      pb[i] = *(const uint4*)(B + (size_t)(N0 + row) * KP + (k0) + c16); \
    } } while (0)
#define S_STORE(buf) do { \
    _Pragma("unroll") \
    for (int i = 0; i < 2; i++) { \
      int ch = tid + i * 256; \
      int row = ch >> 2, c16 = (ch & 3) * 8; \
      *(uint4*)&As[buf][row][c16] = pa[i]; \
      *(uint4*)&Bs[buf][row][c16] = pb[i]; \
    } } while (0)

  G_LOAD(0);
  S_STORE(0);
  __syncthreads();

  for (int c = 0; c < KCH; c++) {
    int buf = c & 1;
    if (c + 1 < KCH) G_LOAD((c + 1) * 32);
#pragma unroll
    for (int kk = 0; kk < 2; kk++) {
      int kb = kk * 16;
      uint32_t a[4][4], b[4][2];
#pragma unroll
      for (int mi = 0; mi < 4; mi++) {
        int row = wm + mi * 16 + (lane & 7) + ((lane >> 3) & 1) * 8;
        int col = kb + ((lane >> 4) << 3);
        uint32_t ad = smem_u32(&As[buf][row][col]);
        asm volatile("ldmatrix.sync.aligned.m8n8.x4.shared.b16 {%0,%1,%2,%3}, [%4];"
                     : "=r"(a[mi][0]), "=r"(a[mi][1]), "=r"(a[mi][2]), "=r"(a[mi][3])
                     : "r"(ad));
      }
#pragma unroll
      for (int ni = 0; ni < 4; ni++) {
        int nr = wn + ni * 8 + (lane & 7);
        int col = kb + (((lane >> 3) & 1) << 3);
        uint32_t bd = smem_u32(&Bs[buf][nr][col]);
        asm volatile("ldmatrix.sync.aligned.m8n8.x2.shared.b16 {%0,%1}, [%2];"
                     : "=r"(b[ni][0]), "=r"(b[ni][1]) : "r"(bd));
      }
#pragma unroll
      for (int mi = 0; mi < 4; mi++)
#pragma unroll
        for (int ni = 0; ni < 4; ni++)
          asm volatile(
              "mma.sync.aligned.m16n8k16.row.col.f32.bf16.bf16.f32 "
              "{%0,%1,%2,%3}, {%4,%5,%6,%7}, {%8,%9}, {%0,%1,%2,%3};"
              : "+f"(acc[mi][ni][0]), "+f"(acc[mi][ni][1]),
                "+f"(acc[mi][ni][2]), "+f"(acc[mi][ni][3])
              : "r"(a[mi][0]), "r"(a[mi][1]), "r"(a[mi][2]), "r"(a[mi][3]),
                "r"(b[ni][0]), "r"(b[ni][1]));
    }
    if (c + 1 < KCH) S_STORE(buf ^ 1);
    __syncthreads();
  }

  int gr = lane >> 2, gc = (lane & 3) * 2;
#pragma unroll
  for (int mi = 0; mi < 4; mi++) {
#pragma unroll
    for (int ni = 0; ni < 4; ni++) {
      int col = N0 + wn + ni * 8 + gc;
      int r0 = M0 + wm + mi * 16 + gr;
      float bx = bias[col], by = bias[col + 1];
      float2 v0 = { acc[mi][ni][0] + bx, acc[mi][ni][1] + by };
      float2 v1 = { acc[mi][ni][2] + bx, acc[mi][ni][3] + by };
      *(float2*)(C + (size_t)r0 * HDIM + col) = v0;
      *(float2*)(C + (size_t)(r0 + 8) * HDIM + col) = v1;
    }
  }
#undef G_LOAD
#undef S_STORE
}

// ============ centroid selection (key(1) gumbel over NC=2) ============
__global__ void centroid_select() {
  int idx = blockIdx.x * blockDim.x + threadIdx.x;  // flat (b,s,h)
  if (idx >= BDIM*SDIM*NH) return;
  int b = idx / (SDIM*NH);
  int r = idx - b*(SDIM*NH);
  int s = r / NH;
  int h = r - s*NH;
  const float* Lk = d_L + (size_t)(b*SDIM + s) * NCOL + 24 + h*2;
  float l0 = Lk[0], l1 = Lk[1];
  unsigned base = 2u * (unsigned)idx;
  float g0 = gumbel_of_u(u_from_v23(tf_bits(0u, 1u, base)      >> 9));
  float g1 = gumbel_of_u(u_from_v23(tf_bits(0u, 1u, base + 1u) >> 9));
  int c = ((l1 + g1) > (l0 + g0)) ? 1 : 0;
  d_code[((b*NH + h) << 10) + s] = (unsigned char)c;
}

// ============ attention selection (key(2) gumbel over S=1024) ============
__device__ __forceinline__ int pick_k(unsigned long long b0, unsigned long long b1,
                                      float D0, float D1) {
  int k0 = 1023 - (int)(b0 & 1023u);
  int k1 = 1023 - (int)(b1 & 1023u);
  float s0 = D0 + gumbel_of_u(u_from_v23((unsigned)(b0 >> 10)));
  float s1 = D1 + gumbel_of_u(u_from_v23((unsigned)(b1 >> 10)));
  if (s0 > s1) return k0;
  if (s1 > s0) return k1;
  return min(k0, k1);
}

__global__ __launch_bounds__(256) void attn_select() {
  int gw = (blockIdx.x * blockDim.x + threadIdx.x) >> 5;
  int lane = threadIdx.x & 31;
  if (gw >= NROWSEL) return;
  int bh = gw >> 10, q = gw & 1023;
  int b = bh / NH, h = bh - b*NH;

  const float* Lq = d_L + (size_t)(b*SDIM + q) * NCOL + h*2;
  float p0 = Lq[0], p1 = Lq[1];

  const unsigned char* cd = d_code + ((size_t)bh << 10);
  unsigned long long best0 = 0ull, best1 = 0ull;
  unsigned base = (unsigned)gw * 1024u;
#pragma unroll 4
  for (int k = lane; k < 1024; k += 32) {
    unsigned bits = tf_bits(0u, 2u, base + (unsigned)k);
    unsigned long long p = (((unsigned long long)(bits >> 9)) << 10) | (unsigned)(1023 - k);
    if (cd[k]) { if (p > best1) best1 = p; } else { if (p > best0) best0 = p; }
  }
#pragma unroll
  for (int o = 16; o; o >>= 1) {
    best0 = max(best0, __shfl_xor_sync(0xffffffffu, best0, o));
    best1 = max(best1, __shfl_xor_sync(0xffffffffu, best1, o));
  }
  if (lane == 0) d_kstar[gw] = pick_k(best0, best1, p0, p1);
}

// ============ gather selected V rows -> split K-folded A' for P GEMM ============
__global__ void gather_split() {
  int t = blockIdx.x * blockDim.x + threadIdx.x;
  if (t >= MROWS*NH*16) return;
  int f  = t & 15;
  int mh = t >> 4;
  int h  = mh % NH;
  int m  = mh / NH;
  int b  = m >> 10, q = m & 1023;
  int ks = d_kstar[((b*NH + h) << 10) + q];
  float4 v = *(const float4*)(d_V + (size_t)(b*SDIM + ks)*HDIM + h*HD + f*4);
  uint2 hv, lv;
  split4(v, hv, lv);
  size_t base = (size_t)m * KP + h*HD + f*4;
  *(uint2*)(d_Agp + base)        = hv;
  *(uint2*)(d_Agp + base + 768)  = hv;
  *(uint2*)(d_Agp + base + 1536) = lv;
}

extern "C" void kernel_launch(void* const* d_in, const int* in_sizes, int n_in,
                              void* d_out, int out_size) {
  // Input mapping. Primary: setup_inputs() dict order. Hedge: alphabetical.
  int iIn=0,iWq=1,ibq=2,iWk=3,ibk=4,iWv=5,ibv=6,iC=7,iWp=8,ibp=9;
  if (in_sizes[0] != MROWS*HDIM) {
    iWk=0; iWp=1; iWq=2; iWv=3; ibk=4; ibp=5; ibq=6; ibv=7; iC=8; iIn=9;
  }
  const float* x    = (const float*)d_in[iIn];
  const float* Wq   = (const float*)d_in[iWq];
  const float* bq   = (const float*)d_in[ibq];
  const float* Wk   = (const float*)d_in[iWk];
  const float* bk   = (const float*)d_in[ibk];
  const float* Wv   = (const float*)d_in[iWv];
  const float* bv   = (const float*)d_in[ibv];
  const float* cent = (const float*)d_in[iC];
  const float* Wp   = (const float*)d_in[iWp];
  const float* bp   = (const float*)d_in[ibp];
  float* out = (float*)d_out;

  float *vbuf;
  cudaGetSymbolAddress((void**)&vbuf, d_V);
  __nv_bfloat16 *ap, *agp, *bvp, *bwp;
  cudaGetSymbolAddress((void**)&ap,  d_Ap);
  cudaGetSymbolAddress((void**)&agp, d_Agp);
  cudaGetSymbolAddress((void**)&bvp, d_Bv);
  cudaGetSymbolAddress((void**)&bwp, d_Bw);

  // logits path (f32, bit-critical for selections)
  prep_wc<<<(HDIM*NCOL + NCOL + 255)/256, 256>>>(Wq, Wk, bq, bk, cent);
  logits_x<<<MROWS/128, 256>>>(x);

  // split-bf16 operand prep (K-folded layouts)
  conv_xsplit<<<(MROWS*192 + 255)/256, 256>>>((const float4*)x);
  conv_wsplit<<<(HDIM*HDIM + 255)/256, 256>>>(Wv, bvp);
  conv_wsplit<<<(HDIM*HDIM + 255)/256, 256>>>(Wp, bwp);

  // V = x @ Wv + bv  (tensor cores via mma.sync)
  dim3 tg(HDIM/128, MROWS/128);
  mma_gemm<<<tg, 256>>>(ap, bvp, bv, vbuf);

  // selections (exact f32 path)
  centroid_select<<<(BDIM*SDIM*NH)/256, 256>>>();
  attn_select<<<(NROWSEL*32)/256, 256>>>();
  gather_split<<<(MROWS*NH*16)/256, 256>>>();

  // out = Ag @ Wp + bp
  mma_gemm<<<tg, 256>>>(agp, bwp, bp, out);
}

// round 8
// speedup vs baseline: 1.7804x; 1.0437x over previous
#include <cuda_runtime.h>
#include <cuda_bf16.h>
#include <cstdint>
#include <math.h>

// Problem constants
#define BDIM 8
#define SDIM 1024
#define HDIM 768
#define NH   12
#define HD   64
#define MROWS (BDIM*SDIM)        // 8192
#define NROWSEL (BDIM*NH*SDIM)   // 98304 rows (b,h,q)
#define NCOL 48                  // 24 q-logit cols | 24 k-logit cols
#define KP   2304                // split-K: [hi|hi|lo] x [hi|lo|hi]
#define KCH  72                  // KP/32 k-chunks
#define TINYF 1.17549435e-38f

// Scratch (allocation-free rule: __device__ globals)
__device__ float d_V[MROWS * HDIM];             // V = x@Wv + bv (f32)
__device__ float d_Wc[HDIM * NCOL];             // folded logit weights
__device__ float d_bc[NCOL];
__device__ float d_L[MROWS * NCOL];             // logits [8192][48] (q|k)
__device__ unsigned char d_code[BDIM*NH*SDIM];
__device__ int d_kstar[BDIM*NH*SDIM];
// split-bf16 GEMM operands (K-folded 3-product layout)
__device__ __nv_bfloat16 d_Ap[MROWS * KP];      // x:  [Ah | Ah | Al]
__device__ __nv_bfloat16 d_Agp[MROWS * KP];     // gathered V, same layout
__device__ __nv_bfloat16 d_Bv[HDIM * KP];       // WvT: [Bh | Bl | Bh]
__device__ __nv_bfloat16 d_Bw[HDIM * KP];       // WpT: [Bh | Bl | Bh]

__device__ __forceinline__ uint32_t smem_u32(const void* p) {
  uint32_t a;
  asm("{ .reg .u64 t; cvta.to.shared.u64 t, %1; cvt.u32.u64 %0, t; }" : "=r"(a) : "l"(p));
  return a;
}

// ======================= JAX threefry2x32 =======================
__device__ __forceinline__ void threefry(unsigned k0, unsigned k1,
                                         unsigned &x0, unsigned &x1) {
  unsigned k2 = k0 ^ k1 ^ 0x1BD11BDAu;
  x0 += k0; x1 += k1;
#define TF_R(r) { x0 += x1; x1 = __funnelshift_l(x1, x1, r); x1 ^= x0; }
  TF_R(13) TF_R(15) TF_R(26) TF_R(6)
  x0 += k1; x1 += k2 + 1u;
  TF_R(17) TF_R(29) TF_R(16) TF_R(24)
  x0 += k2; x1 += k0 + 2u;
  TF_R(13) TF_R(15) TF_R(26) TF_R(6)
  x0 += k0; x1 += k1 + 3u;
  TF_R(17) TF_R(29) TF_R(16) TF_R(24)
  x0 += k1; x1 += k2 + 4u;
  TF_R(13) TF_R(15) TF_R(26) TF_R(6)
  x0 += k2; x1 += k0 + 5u;
#undef TF_R
}
__device__ __forceinline__ unsigned tf_bits(unsigned k0, unsigned k1, unsigned lo) {
  unsigned x0 = 0u, x1 = lo;
  threefry(k0, k1, x0, x1);
  return x0 ^ x1;
}
__device__ __forceinline__ float u_from_v23(unsigned v23) {
  float f = __uint_as_float(v23 | 0x3f800000u) - 1.0f;
  return fmaxf(f, TINYF);
}
__device__ __forceinline__ float gumbel_of_u(float u) {
  return (float)(-log(-log((double)u)));
}

// ============ split helper ============
__device__ __forceinline__ void split4(float4 v, uint2 &h, uint2 &l) {
  unsigned short hx = __bfloat16_as_ushort(__float2bfloat16(v.x));
  unsigned short hy = __bfloat16_as_ushort(__float2bfloat16(v.y));
  unsigned short hz = __bfloat16_as_ushort(__float2bfloat16(v.z));
  unsigned short hw = __bfloat16_as_ushort(__float2bfloat16(v.w));
  unsigned short lx = __bfloat16_as_ushort(__float2bfloat16(v.x - __bfloat162float(__ushort_as_bfloat16(hx))));
  unsigned short ly = __bfloat16_as_ushort(__float2bfloat16(v.y - __bfloat162float(__ushort_as_bfloat16(hy))));
  unsigned short lz = __bfloat16_as_ushort(__float2bfloat16(v.z - __bfloat162float(__ushort_as_bfloat16(hz))));
  unsigned short lw = __bfloat16_as_ushort(__float2bfloat16(v.w - __bfloat162float(__ushort_as_bfloat16(hw))));
  h = make_uint2((unsigned)hx | ((unsigned)hy << 16), (unsigned)hz | ((unsigned)hw << 16));
  l = make_uint2((unsigned)lx | ((unsigned)ly << 16), (unsigned)lz | ((unsigned)lw << 16));
}

// ============ fused prep: conv_xsplit | conv_wsplit(Wv) | conv_wsplit(Wp) | prep_wc
#define NB_X   6144
#define NB_W   2304
#define NB_WC  145
#define NB_PREP (NB_X + 2*NB_W + NB_WC)
__global__ __launch_bounds__(256) void prep_all(
    const float* __restrict__ x,
    const float* __restrict__ Wv, const float* __restrict__ Wp,
    const float* __restrict__ Wq, const float* __restrict__ Wk,
    const float* __restrict__ bq, const float* __restrict__ bk,
    const float* __restrict__ cent)
{
  int blk = blockIdx.x, tid = threadIdx.x;
  if (blk < NB_X) {
    // x [8192][768] f32 -> d_Ap [8192][2304] = [Ah | Ah | Al]
    int i = blk * 256 + tid;
    int row = i / 192, c4 = (i - row * 192) * 4;
    uint2 h, l;
    split4(((const float4*)x)[i], h, l);
    size_t base = (size_t)row * KP + c4;
    *(uint2*)(d_Ap + base)        = h;
    *(uint2*)(d_Ap + base + 768)  = h;
    *(uint2*)(d_Ap + base + 1536) = l;
  } else if (blk < NB_X + 2*NB_W) {
    int wi = blk - NB_X;
    const float* W = (wi < NB_W) ? Wv : Wp;
    __nv_bfloat16* Bp = (wi < NB_W) ? d_Bv : d_Bw;
    int idx = (wi % NB_W) * 256 + tid;
    int n = idx / HDIM, k = idx - n * HDIM;
    float v = W[(size_t)k * HDIM + n];
    __nv_bfloat16 hb = __float2bfloat16(v);
    __nv_bfloat16 lb = __float2bfloat16(v - __bfloat162float(hb));
    size_t base = (size_t)n * KP;
    Bp[base + k]        = hb;
    Bp[base + 768 + k]  = lb;
    Bp[base + 1536 + k] = hb;
  } else {
    int t = (blk - NB_X - 2*NB_W) * 256 + tid;
    if (t < HDIM * NCOL) {
      int row = t / NCOL, j = t - row * NCOL;
      const float* W = (j < 24) ? Wq : Wk;
      int h = (j % 24) >> 1, c = j & 1;
      float s = 0.f;
#pragma unroll
      for (int d = 0; d < HD; d++)
        s += W[row * HDIM + h * HD + d] * cent[d * 2 + c];
      d_Wc[row * NCOL + j] = s;
    } else if (t < HDIM * NCOL + NCOL) {
      int j = t - HDIM * NCOL;
      const float* bb = (j < 24) ? bq : bk;
      int h = (j % 24) >> 1, c = j & 1;
      float s = 0.f;
#pragma unroll
      for (int d = 0; d < HD; d++)
        s += bb[h * HD + d] * cent[d * 2 + c];
      d_bc[j] = s;
    }
  }
}

// ============ logits L = x@Wc+bc  (+fused centroid codes) ============
// 128 blocks of 64 rows; 256 threads: r = tid&63 (row), g = tid>>6 (12-col group)
__global__ __launch_bounds__(256) void logits_centroid(const float* __restrict__ x) {
  __shared__ float Xs[64][65];
  __shared__ float Ws[64][NCOL];
  int tid = threadIdx.x;
  int row0 = blockIdx.x * 64;
  int r = tid & 63, g = tid >> 6;

  float acc[12] = {};

  for (int k0 = 0; k0 < HDIM; k0 += 64) {
    __syncthreads();
#pragma unroll
    for (int i = 0; i < 4; i++) {            // 1024 float4 / 256 threads
      int f4 = tid + i * 256;
      int fr = f4 >> 4, fc = (f4 & 15) * 4;
      float4 v = *(const float4*)(x + (size_t)(row0 + fr) * HDIM + k0 + fc);
      Xs[fr][fc+0] = v.x; Xs[fr][fc+1] = v.y; Xs[fr][fc+2] = v.z; Xs[fr][fc+3] = v.w;
    }
#pragma unroll
    for (int i = 0; i < 3; i++) {            // 768 float4 / 256 threads
      int f4 = tid + i * 256;
      int wr = f4 / 12, wc = (f4 % 12) * 4;
      *(float4*)&Ws[wr][wc] = *(const float4*)(d_Wc + (size_t)(k0 + wr) * NCOL + wc);
    }
    __syncthreads();
#pragma unroll 4
    for (int kk = 0; kk < 64; kk++) {
      float xv = Xs[r][kk];
      const float4* w4 = (const float4*)&Ws[kk][g * 12];
#pragma unroll
      for (int q4 = 0; q4 < 3; q4++) {
        float4 w = w4[q4];
        acc[q4*4+0] += xv * w.x;
        acc[q4*4+1] += xv * w.y;
        acc[q4*4+2] += xv * w.z;
        acc[q4*4+3] += xv * w.w;
      }
    }
  }
  float* Lp = d_L + (size_t)(row0 + r) * NCOL + g * 12;
#pragma unroll
  for (int q4 = 0; q4 < 3; q4++) {
    float4 o;
    o.x = acc[q4*4+0] + d_bc[g*12 + q4*4+0];
    o.y = acc[q4*4+1] + d_bc[g*12 + q4*4+1];
    o.z = acc[q4*4+2] + d_bc[g*12 + q4*4+2];
    o.w = acc[q4*4+3] + d_bc[g*12 + q4*4+3];
    *(float4*)(Lp + q4*4) = o;
  }
  __syncthreads();   // block's d_L writes visible to block's reads below

  // fused centroid selection: 64 rows x 12 heads = 768 codes, 3 per thread
#pragma unroll
  for (int i = 0; i < 3; i++) {
    int e = tid + i * 256;                   // 0..767
    int rl = e / 12, h = e - rl * 12;
    int m = row0 + rl;                       // global row = b*1024+s
    int b = m >> 10, s = m & 1023;
    const float* Lk = d_L + (size_t)m * NCOL + 24 + h * 2;
    float l0 = Lk[0], l1 = Lk[1];
    unsigned base = 2u * (unsigned)(m * NH + h);  // flat idx into [B,S,NH,NC]
    float g0 = gumbel_of_u(u_from_v23(tf_bits(0u, 1u, base)      >> 9));
    float g1 = gumbel_of_u(u_from_v23(tf_bits(0u, 1u, base + 1u) >> 9));
    int c = ((l1 + g1) > (l0 + g0)) ? 1 : 0;
    d_code[((b*NH + h) << 10) + s] = (unsigned char)c;
  }
}

// ============ attention row selection helper ============
__device__ __forceinline__ int pick_k(unsigned long long b0, unsigned long long b1,
                                      float D0, float D1) {
  int k0 = 1023 - (int)(b0 & 1023u);
  int k1 = 1023 - (int)(b1 & 1023u);
  float s0 = D0 + gumbel_of_u(u_from_v23((unsigned)(b0 >> 10)));
  float s1 = D1 + gumbel_of_u(u_from_v23((unsigned)(b1 >> 10)));
  if (s0 > s1) return k0;
  if (s1 > s0) return k1;
  return min(k0, k1);
}

// ============ FAT kernel: V-GEMM (blocks 0..383) || attn_select (rest) =======
// GEMM: C[8192,768] = A'@B'^T + bias, A'[M][2304], B'[768][2304], f32 out.
#define GEMM_NB 384
#define ATTN_NB (NROWSEL/8)   // 12288 blocks, 8 warp-rows each
__global__ __launch_bounds__(256) void fat_vgemm_attn(
    const __nv_bfloat16* __restrict__ A, const __nv_bfloat16* __restrict__ B,
    const float* __restrict__ bias, float* __restrict__ C)
{
  __shared__ __nv_bfloat16 As[2][128][40];   // 80B row stride: conflict-free ldmatrix
  __shared__ __nv_bfloat16 Bs[2][128][40];
  int tid = threadIdx.x;

  if (blockIdx.x < GEMM_NB) {
    // ----------------- GEMM branch -----------------
    int wid = tid >> 5, lane = tid & 31;
    int bn = blockIdx.x % 6, bm = blockIdx.x / 6;
    int M0 = bm * 128, N0 = bn * 128;
    int wm = (wid & 1) * 64, wn = (wid >> 1) * 32;

    float acc[4][4][4] = {};
    uint4 pa[2], pb[2];
#define G_LOAD(k0) do { \
      _Pragma("unroll") \
      for (int i = 0; i < 2; i++) { \
        int ch = tid + i * 256; \
        int row = ch >> 2, c16 = (ch & 3) * 8; \
        pa[i] = *(const uint4*)(A + (size_t)(M0 + row) * KP + (k0) + c16); \
        pb[i] = *(const uint4*)(B + (size_t)(N0 + row) * KP + (k0) + c16); \
      } } while (0)
#define S_STORE(buf) do { \
      _Pragma("unroll") \
      for (int i = 0; i < 2; i++) { \
        int ch = tid + i * 256; \
        int row = ch >> 2, c16 = (ch & 3) * 8; \
        *(uint4*)&As[buf][row][c16] = pa[i]; \
        *(uint4*)&Bs[buf][row][c16] = pb[i]; \
      } } while (0)

    G_LOAD(0);
    S_STORE(0);
    __syncthreads();

    for (int c = 0; c < KCH; c++) {
      int buf = c & 1;
      if (c + 1 < KCH) G_LOAD((c + 1) * 32);
#pragma unroll
      for (int kk = 0; kk < 2; kk++) {
        int kb = kk * 16;
        uint32_t a[4][4], b[4][2];
#pragma unroll
        for (int mi = 0; mi < 4; mi++) {
          int row = wm + mi * 16 + (lane & 7) + ((lane >> 3) & 1) * 8;
          int col = kb + ((lane >> 4) << 3);
          uint32_t ad = smem_u32(&As[buf][row][col]);
          asm volatile("ldmatrix.sync.aligned.m8n8.x4.shared.b16 {%0,%1,%2,%3}, [%4];"
                       : "=r"(a[mi][0]), "=r"(a[mi][1]), "=r"(a[mi][2]), "=r"(a[mi][3])
                       : "r"(ad));
        }
#pragma unroll
        for (int ni = 0; ni < 4; ni++) {
          int nr = wn + ni * 8 + (lane & 7);
          int col = kb + (((lane >> 3) & 1) << 3);
          uint32_t bd = smem_u32(&Bs[buf][nr][col]);
          asm volatile("ldmatrix.sync.aligned.m8n8.x2.shared.b16 {%0,%1}, [%2];"
                       : "=r"(b[ni][0]), "=r"(b[ni][1]) : "r"(bd));
        }
#pragma unroll
        for (int mi = 0; mi < 4; mi++)
#pragma unroll
          for (int ni = 0; ni < 4; ni++)
            asm volatile(
                "mma.sync.aligned.m16n8k16.row.col.f32.bf16.bf16.f32 "
                "{%0,%1,%2,%3}, {%4,%5,%6,%7}, {%8,%9}, {%0,%1,%2,%3};"
                : "+f"(acc[mi][ni][0]), "+f"(acc[mi][ni][1]),
                  "+f"(acc[mi][ni][2]), "+f"(acc[mi][ni][3])
                : "r"(a[mi][0]), "r"(a[mi][1]), "r"(a[mi][2]), "r"(a[mi][3]),
                  "r"(b[ni][0]), "r"(b[ni][1]));
      }
      if (c + 1 < KCH) S_STORE(buf ^ 1);
      __syncthreads();
    }

    int gr = lane >> 2, gc = (lane & 3) * 2;
#pragma unroll
    for (int mi = 0; mi < 4; mi++) {
#pragma unroll
      for (int ni = 0; ni < 4; ni++) {
        int col = N0 + wn + ni * 8 + gc;
        int r0 = M0 + wm + mi * 16 + gr;
        float bx = bias[col], by = bias[col + 1];
        float2 v0 = { acc[mi][ni][0] + bx, acc[mi][ni][1] + by };
        float2 v1 = { acc[mi][ni][2] + bx, acc[mi][ni][3] + by };
        *(float2*)(C + (size_t)r0 * HDIM + col) = v0;
        *(float2*)(C + (size_t)(r0 + 8) * HDIM + col) = v1;
      }
    }
#undef G_LOAD
#undef S_STORE
  } else {
    // ----------------- attn_select branch -----------------
    int gw = ((blockIdx.x - GEMM_NB) * 256 + tid) >> 5;  // (b,h,q) row id
    int lane = tid & 31;
    int bh = gw >> 10, q = gw & 1023;
    int b = bh / NH, h = bh - b*NH;

    const float* Lq = d_L + (size_t)(b*SDIM + q) * NCOL + h*2;
    float p0 = Lq[0], p1 = Lq[1];

    const unsigned char* cd = d_code + ((size_t)bh << 10);
    unsigned long long best0 = 0ull, best1 = 0ull;
    unsigned base = (unsigned)gw * 1024u;
#pragma unroll 4
    for (int k = lane; k < 1024; k += 32) {
      unsigned bits = tf_bits(0u, 2u, base + (unsigned)k);
      unsigned long long p = (((unsigned long long)(bits >> 9)) << 10) | (unsigned)(1023 - k);
      if (cd[k]) { if (p > best1) best1 = p; } else { if (p > best0) best0 = p; }
    }
#pragma unroll
    for (int o = 16; o; o >>= 1) {
      best0 = max(best0, __shfl_xor_sync(0xffffffffu, best0, o));
      best1 = max(best1, __shfl_xor_sync(0xffffffffu, best1, o));
    }
    if (lane == 0) d_kstar[gw] = pick_k(best0, best1, p0, p1);
  }
}

// ============ standalone GEMM for the P projection ============
__global__ __launch_bounds__(256) void mma_gemm(
    const __nv_bfloat16* __restrict__ A, const __nv_bfloat16* __restrict__ B,
    const float* __restrict__ bias, float* __restrict__ C)
{
  __shared__ __nv_bfloat16 As[2][128][40];
  __shared__ __nv_bfloat16 Bs[2][128][40];
  int tid = threadIdx.x;
  int wid = tid >> 5, lane = tid & 31;
  int M0 = blockIdx.y * 128, N0 = blockIdx.x * 128;
  int wm = (wid & 1) * 64, wn = (wid >> 1) * 32;

  float acc[4][4][4] = {};
  uint4 pa[2], pb[2];
#define G_LOAD(k0) do { \
    _Pragma("unroll") \
    for (int i = 0; i < 2; i++) { \
      int ch = tid + i * 256; \
      int row = ch >> 2, c16 = (ch & 3) * 8; \
      pa[i] = *(const uint4*)(A + (size_t)(M0 + row) * KP + (k0) + c16); \
      pb[i] = *(const uint4*)(B + (size_t)(N0 + row) * KP + (k0) + c16); \
    } } while (0)
#define S_STORE(buf) do { \
    _Pragma("unroll") \
    for (int i = 0; i < 2; i++) { \
      int ch = tid + i * 256; \
      int row = ch >> 2, c16 = (ch & 3) * 8; \
      *(uint4*)&As[buf][row][c16] = pa[i]; \
      *(uint4*)&Bs[buf][row][c16] = pb[i]; \
    } } while (0)

  G_LOAD(0);
  S_STORE(0);
  __syncthreads();

  for (int c = 0; c < KCH; c++) {
    int buf = c & 1;
    if (c + 1 < KCH) G_LOAD((c + 1) * 32);
#pragma unroll
    for (int kk = 0; kk < 2; kk++) {
      int kb = kk * 16;
      uint32_t a[4][4], b[4][2];
#pragma unroll
      for (int mi = 0; mi < 4; mi++) {
        int row = wm + mi * 16 + (lane & 7) + ((lane >> 3) & 1) * 8;
        int col = kb + ((lane >> 4) << 3);
        uint32_t ad = smem_u32(&As[buf][row][col]);
        asm volatile("ldmatrix.sync.aligned.m8n8.x4.shared.b16 {%0,%1,%2,%3}, [%4];"
                     : "=r"(a[mi][0]), "=r"(a[mi][1]), "=r"(a[mi][2]), "=r"(a[mi][3])
                     : "r"(ad));
      }
#pragma unroll
      for (int ni = 0; ni < 4; ni++) {
        int nr = wn + ni * 8 + (lane & 7);
        int col = kb + (((lane >> 3) & 1) << 3);
        uint32_t bd = smem_u32(&Bs[buf][nr][col]);
        asm volatile("ldmatrix.sync.aligned.m8n8.x2.shared.b16 {%0,%1}, [%2];"
                     : "=r"(b[ni][0]), "=r"(b[ni][1]) : "r"(bd));
      }
#pragma unroll
      for (int mi = 0; mi < 4; mi++)
#pragma unroll
        for (int ni = 0; ni < 4; ni++)
          asm volatile(
              "mma.sync.aligned.m16n8k16.row.col.f32.bf16.bf16.f32 "
              "{%0,%1,%2,%3}, {%4,%5,%6,%7}, {%8,%9}, {%0,%1,%2,%3};"
              : "+f"(acc[mi][ni][0]), "+f"(acc[mi][ni][1]),
                "+f"(acc[mi][ni][2]), "+f"(acc[mi][ni][3])
              : "r"(a[mi][0]), "r"(a[mi][1]), "r"(a[mi][2]), "r"(a[mi][3]),
                "r"(b[ni][0]), "r"(b[ni][1]));
    }
    if (c + 1 < KCH) S_STORE(buf ^ 1);
    __syncthreads();
  }

  int gr = lane >> 2, gc = (lane & 3) * 2;
#pragma unroll
  for (int mi = 0; mi < 4; mi++) {
#pragma unroll
    for (int ni = 0; ni < 4; ni++) {
      int col = N0 + wn + ni * 8 + gc;
      int r0 = M0 + wm + mi * 16 + gr;
      float bx = bias[col], by = bias[col + 1];
      float2 v0 = { acc[mi][ni][0] + bx, acc[mi][ni][1] + by };
      float2 v1 = { acc[mi][ni][2] + bx, acc[mi][ni][3] + by };
      *(float2*)(C + (size_t)r0 * HDIM + col) = v0;
      *(float2*)(C + (size_t)(r0 + 8) * HDIM + col) = v1;
    }
  }
#undef G_LOAD
#undef S_STORE
}

// ============ gather selected V rows -> split K-folded A' for P GEMM ============
__global__ void gather_split() {
  int t = blockIdx.x * blockDim.x + threadIdx.x;
  if (t >= MROWS*NH*16) return;
  int f  = t & 15;
  int mh = t >> 4;
  int h  = mh % NH;
  int m  = mh / NH;
  int b  = m >> 10, q = m & 1023;
  int ks = d_kstar[((b*NH + h) << 10) + q];
  float4 v = *(const float4*)(d_V + (size_t)(b*SDIM + ks)*HDIM + h*HD + f*4);
  uint2 hv, lv;
  split4(v, hv, lv);
  size_t base = (size_t)m * KP + h*HD + f*4;
  *(uint2*)(d_Agp + base)        = hv;
  *(uint2*)(d_Agp + base + 768)  = hv;
  *(uint2*)(d_Agp + base + 1536) = lv;
}

extern "C" void kernel_launch(void* const* d_in, const int* in_sizes, int n_in,
                              void* d_out, int out_size) {
  // Input mapping. Primary: setup_inputs() dict order. Hedge: alphabetical.
  int iIn=0,iWq=1,ibq=2,iWk=3,ibk=4,iWv=5,ibv=6,iC=7,iWp=8,ibp=9;
  if (in_sizes[0] != MROWS*HDIM) {
    iWk=0; iWp=1; iWq=2; iWv=3; ibk=4; ibp=5; ibq=6; ibv=7; iC=8; iIn=9;
  }
  const float* x    = (const float*)d_in[iIn];
  const float* Wq   = (const float*)d_in[iWq];
  const float* bq   = (const float*)d_in[ibq];
  const float* Wk   = (const float*)d_in[iWk];
  const float* bk   = (const float*)d_in[ibk];
  const float* Wv   = (const float*)d_in[iWv];
  const float* bv   = (const float*)d_in[ibv];
  const float* cent = (const float*)d_in[iC];
  const float* Wp   = (const float*)d_in[iWp];
  const float* bp   = (const float*)d_in[ibp];
  float* out = (float*)d_out;

  float *vbuf;
  cudaGetSymbolAddress((void**)&vbuf, d_V);
  __nv_bfloat16 *ap, *agp, *bvp, *bwp;
  cudaGetSymbolAddress((void**)&ap,  d_Ap);
  cudaGetSymbolAddress((void**)&agp, d_Agp);
  cudaGetSymbolAddress((void**)&bvp, d_Bv);
  cudaGetSymbolAddress((void**)&bwp, d_Bw);

  // 1) all operand prep (independent pieces, one launch)
  prep_all<<<NB_PREP, 256>>>(x, Wv, Wp, Wq, Wk, bq, bk, cent);

  // 2) logits + fused centroid codes
  logits_centroid<<<MROWS/64, 256>>>(x);

  // 3) FAT: V-GEMM overlapped with attention threefry scan
  fat_vgemm_attn<<<GEMM_NB + ATTN_NB, 256>>>(ap, bvp, bv, vbuf);

  // 4) gather + split for P GEMM
  gather_split<<<(MROWS*NH*16)/256, 256>>>();

  // 5) out = Ag @ Wp + bp
  dim3 tg(HDIM/128, MROWS/128);
  mma_gemm<<<tg, 256>>>(agp, bwp, bp, out);
}